// round 4
// baseline (speedup 1.0000x reference)
#include <cuda_runtime.h>
#include <cstdint>
#include <cstddef>

typedef unsigned long long ull;

// ---------------- problem constants ----------------
#define STEPS 100
#define BATCH 64
#define NSPK  (STEPS*BATCH*3*32*32)   // 19,660,800
#define XSZ   (BATCH*3*32*32)         // 196,608
#define N1    (BATCH*32*14*14)        // 401,408  (layer-1 neurons per step)
#define N2    (BATCH*64*5*5)          // 102,400  (layer-2 neurons per step)
#define TB    (STEPS*BATCH)           // 6400

// ---------------- scratch (device globals; no cudaMalloc allowed) ----------
__device__ unsigned char g_spk0[NSPK];                        // poisson spikes [t][b][c][h][w]
__device__ __align__(16) float g_curin[(size_t)STEPS*N1];     // [t][b][sp196][oc32]
__device__ unsigned int  g_spk1[(size_t)STEPS*BATCH*196];     // [t][b*196+sp] -> 32-bit oc mask
__device__ __align__(16) float g_curh1[(size_t)STEPS*N2];     // [t][b][oc64*25+sp]
__device__ unsigned char g_spkh1[(size_t)STEPS*N2];           // same layout, bytes
__device__ float         g_fc[STEPS*BATCH*10];
__device__ __align__(16) float g_Wp1[3*36*32];                // pooled conv1 W [c][uv6x6][oc32]
__device__ __align__(16) float g_Wp2[32*36*64];               // pooled conv2 W [c][uv6x6][oc64]

// ---------------- packed f32x2 helpers (bit-exact fp32 pairs) --------------
__device__ __forceinline__ void ffma2(ull& d, ull a, ull b) {
    asm("fma.rn.f32x2 %0, %1, %2, %0;" : "+l"(d) : "l"(a), "l"(b));
}
__device__ __forceinline__ void fadd2(ull& d, ull a) {
    asm("add.rn.f32x2 %0, %0, %1;" : "+l"(d) : "l"(a));
}
__device__ __forceinline__ ull pack_dup(float f) {
    ull p; asm("mov.b64 %0, {%1, %1};" : "=l"(p) : "f"(f)); return p;
}
__device__ __forceinline__ void unpack2(ull p, float& lo, float& hi) {
    asm("mov.b64 {%0, %1}, %2;" : "=f"(lo), "=f"(hi) : "l"(p));
}

// ---------------- threefry2x32 (JAX-exact, partitionable path) -------------
__device__ __forceinline__ uint2 threefry2x32(uint32_t k0, uint32_t k1,
                                              uint32_t x0, uint32_t x1) {
    uint32_t ks0 = k0, ks1 = k1, ks2 = k0 ^ k1 ^ 0x1BD11BDAu;
    x0 += ks0; x1 += ks1;
#define TFR(r) { x0 += x1; x1 = (x1 << (r)) | (x1 >> (32 - (r))); x1 ^= x0; }
    TFR(13) TFR(15) TFR(26) TFR(6)
    x0 += ks1; x1 += ks2 + 1u;
    TFR(17) TFR(29) TFR(16) TFR(24)
    x0 += ks2; x1 += ks0 + 2u;
    TFR(13) TFR(15) TFR(26) TFR(6)
    x0 += ks0; x1 += ks1 + 3u;
    TFR(17) TFR(29) TFR(16) TFR(24)
    x0 += ks1; x1 += ks2 + 4u;
    TFR(13) TFR(15) TFR(26) TFR(6)
    x0 += ks2; x1 += ks0 + 5u;
#undef TFR
    return make_uint2(x0, x1);
}

// ---------------- k0: fold avgpool(2x2,*0.25) into conv weights ------------
__global__ void k_fold(const float* __restrict__ Win, const float* __restrict__ Wh1) {
    int i = blockIdx.x * blockDim.x + threadIdx.x;
    if (i < 3*36*32) {
        int oc = i & 31; int r = i >> 5; int uv = r % 36; int c = r / 36;
        int u = uv / 6, v = uv % 6;
        float s = 0.f;
        #pragma unroll
        for (int dh = 0; dh < 2; dh++)
            #pragma unroll
            for (int dw = 0; dw < 2; dw++) {
                int kh = u - dh, kw = v - dw;
                if (kh >= 0 && kh < 5 && kw >= 0 && kw < 5)
                    s += Win[(oc*3 + c)*25 + kh*5 + kw];
            }
        g_Wp1[i] = 0.25f * s;
    }
    if (i < 32*36*64) {
        int oc = i & 63; int r = i >> 6; int uv = r % 36; int c = r / 36;
        int u = uv / 6, v = uv % 6;
        float s = 0.f;
        #pragma unroll
        for (int dh = 0; dh < 2; dh++)
            #pragma unroll
            for (int dw = 0; dw < 2; dw++) {
                int kh = u - dh, kw = v - dw;
                if (kh >= 0 && kh < 5 && kw >= 0 && kw < 5)
                    s += Wh1[(oc*32 + c)*25 + kh*5 + kw];
            }
        g_Wp2[i] = 0.25f * s;
    }
}

// ---------------- k1: poisson spike generation -----------------------------
__global__ void k_spikes(const float* __restrict__ x) {
    int i = blockIdx.x * blockDim.x + threadIdx.x;
    if (i >= NSPK) return;
    uint2 r = threefry2x32(0u, 1u, 0u, (uint32_t)i);
    uint32_t bits = r.x ^ r.y;
    float u = __uint_as_float((bits >> 9) | 0x3f800000u) - 1.0f;
    int pos = i % XSZ;
    g_spk0[i] = (u < x[pos] * 2.0f) ? 1 : 0;
}

// ---------------- k2: conv1+pool (pooled 6x6 kernel), f32x2 ----------------
// block per (t,b); 112 threads; thread = 2 spatial outputs x 32 oc
__global__ __launch_bounds__(112) void k_conv1(void) {
    __shared__ float sIn[3*32*32];
    __shared__ __align__(16) float sW[3*36*32];
    int tb = blockIdx.x;
    int tid = threadIdx.x;
    const unsigned char* inp = g_spk0 + (size_t)tb * 3072;
    for (int i = tid; i < 3072; i += 112) sIn[i] = (float)inp[i];
    for (int i = tid; i < 3456; i += 112) sW[i] = g_Wp1[i];
    __syncthreads();
    if (tid >= 98) return;

    int spa = tid, spb = tid + 98;
    int ia = (spa/14)*64 + (spa%14)*2;      // (2ph)*32 + 2pw
    int ib = (spb/14)*64 + (spb%14)*2;
    ull accA[16], accB[16];
    #pragma unroll
    for (int j = 0; j < 16; j++) { accA[j] = 0ull; accB[j] = 0ull; }

    #pragma unroll 1
    for (int c = 0; c < 3; c++) {
        const float* sIc = &sIn[c*1024];
        const ull* wc = (const ull*)&sW[c*1152];
        #pragma unroll 1
        for (int u = 0; u < 6; u++) {
            #pragma unroll
            for (int v = 0; v < 6; v++) {
                ull sa = pack_dup(sIc[ia + u*32 + v]);
                ull sb = pack_dup(sIc[ib + u*32 + v]);
                const ull* w = wc + (u*6 + v)*16;
                #pragma unroll
                for (int j = 0; j < 16; j++) {
                    ull wj = w[j];
                    ffma2(accA[j], wj, sa);
                    ffma2(accB[j], wj, sb);
                }
            }
        }
    }
    ull* oA = (ull*)&g_curin[(size_t)tb*6272 + spa*32];
    ull* oB = (ull*)&g_curin[(size_t)tb*6272 + spb*32];
    #pragma unroll
    for (int j = 0; j < 16; j++) { oA[j] = accA[j]; oB[j] = accB[j]; }
}

// ---------------- k3: LIF scan layer 1 -> ballot bitmasks ------------------
// warp = 32 oc of one (b,sp); lane = oc
__global__ void k_lif1(void) {
    int n = blockIdx.x*256 + threadIdx.x;      // < 401408
    int lane = threadIdx.x & 31;
    int bs = n >> 5;                            // b*196 + sp
    const float* cur = g_curin + n;
    unsigned* out = g_spk1 + bs;
    float spk = 0.f;
    #pragma unroll 1
    for (int t = 0; t < STEPS; t += 4) {
        float c0 = cur[(size_t)(t+0)*N1];
        float c1 = cur[(size_t)(t+1)*N1];
        float c2 = cur[(size_t)(t+2)*N1];
        float c3 = cur[(size_t)(t+3)*N1];
        float mem; unsigned m0, m1, m2, m3;
        mem = c0 - spk; spk = (mem > 1.f) ? 1.f : 0.f; m0 = __ballot_sync(0xffffffffu, mem > 1.f);
        mem = c1 - spk; spk = (mem > 1.f) ? 1.f : 0.f; m1 = __ballot_sync(0xffffffffu, mem > 1.f);
        mem = c2 - spk; spk = (mem > 1.f) ? 1.f : 0.f; m2 = __ballot_sync(0xffffffffu, mem > 1.f);
        mem = c3 - spk; spk = (mem > 1.f) ? 1.f : 0.f; m3 = __ballot_sync(0xffffffffu, mem > 1.f);
        if (lane == 0) {
            out[(size_t)(t+0)*12544] = m0;
            out[(size_t)(t+1)*12544] = m1;
            out[(size_t)(t+2)*12544] = m2;
            out[(size_t)(t+3)*12544] = m3;
        }
    }
}

// ---------------- k4: conv2+pool, weights resident in smem, mask-sparse ----
// block = (b, oc-half, t-half); 50 (t,b) pairs per block; 150KB dynamic smem
#define C2_WF   (32*36*32)                      // 36864 floats of weights
#define C2_DYN  ((C2_WF + 196 + 32*14) * 4)     // bytes
__global__ __launch_bounds__(256) void k_conv2(void) {
    extern __shared__ float dynsm[];
    float*    sW    = dynsm;                    // [c][uv][ocl(32)]
    unsigned* sMask = (unsigned*)(dynsm + C2_WF);   // 196 oc-masks
    unsigned* sRow  = sMask + 196;              // [c][ih(14)] row bitmasks

    int tid = threadIdx.x;
    int b   = blockIdx.x & 63;
    int och = (blockIdx.x >> 6) & 1;
    int th  = blockIdx.x >> 7;

    // stage oc-half weights once per block
    for (int i = tid; i < C2_WF; i += 256) {
        int c = i / 1152; int r = i % 1152; int uv = r >> 5; int ocl = r & 31;
        sW[i] = g_Wp2[c*2304 + uv*64 + och*32 + ocl];
    }

    int active = (tid < 200);
    int sp = tid >> 3, og = tid & 7;            // sp 0..24, oc-quad og
    int ph = sp / 5, pw = sp % 5;
    int shift = 2*pw;

    #pragma unroll 1
    for (int tt = 0; tt < 50; tt++) {
        int t  = th*50 + tt;
        int tb = t*64 + b;
        __syncthreads();                        // weights (first iter) / mask reuse
        if (tid < 196) sMask[tid] = g_spk1[(size_t)t*12544 + b*196 + tid];
        __syncthreads();
        if (tid < 224) {                        // transpose: per-channel row masks
            int c = tid & 31; int rp = tid >> 5;       // rp 0..6
            #pragma unroll
            for (int rr = 0; rr < 2; rr++) {
                int ih = rp*2 + rr;
                unsigned m = 0;
                #pragma unroll
                for (int iw = 0; iw < 14; iw++)
                    m |= ((sMask[ih*14 + iw] >> c) & 1u) << iw;
                sRow[c*14 + ih] = m;
            }
        }
        __syncthreads();
        if (active) {
            ull a0 = 0ull, a1 = 0ull;
            #pragma unroll 1
            for (int c = 0; c < 32; c++) {
                const float* wc = &sW[c*1152];
                const unsigned* rc = &sRow[c*14 + 2*ph];
                #pragma unroll
                for (int u = 0; u < 6; u++) {
                    unsigned bits = (rc[u] >> shift) & 63u;
                    while (bits) {
                        int v = __ffs(bits) - 1; bits &= bits - 1;
                        const ull* w = (const ull*)&wc[(u*6 + v)*32 + og*4];
                        fadd2(a0, w[0]); fadd2(a1, w[1]);
                    }
                }
            }
            float f0, f1, f2, f3; unpack2(a0, f0, f1); unpack2(a1, f2, f3);
            size_t ob = (size_t)tb*1600 + (size_t)(och*32 + og*4)*25 + sp;
            g_curh1[ob] = f0; g_curh1[ob+25] = f1; g_curh1[ob+50] = f2; g_curh1[ob+75] = f3;
        }
    }
}

// ---------------- k5: LIF scan layer 2 (float4, unroll2) -------------------
__global__ void k_lif2(void) {
    int q = blockIdx.x*256 + threadIdx.x;       // < 25600 float4-neurons
    const float4* cur = (const float4*)g_curh1;
    uchar4* out = (uchar4*)g_spkh1;
    float s0 = 0.f, s1 = 0.f, s2 = 0.f, s3 = 0.f;
    #pragma unroll 1
    for (int t = 0; t < STEPS; t += 2) {
        float4 a = cur[(size_t)(t+0)*25600 + q];
        float4 b = cur[(size_t)(t+1)*25600 + q];
        float m; uchar4 o;
        m = a.x - s0; s0 = (m > 1.f) ? 1.f : 0.f; o.x = (unsigned char)(m > 1.f);
        m = a.y - s1; s1 = (m > 1.f) ? 1.f : 0.f; o.y = (unsigned char)(m > 1.f);
        m = a.z - s2; s2 = (m > 1.f) ? 1.f : 0.f; o.z = (unsigned char)(m > 1.f);
        m = a.w - s3; s3 = (m > 1.f) ? 1.f : 0.f; o.w = (unsigned char)(m > 1.f);
        out[(size_t)(t+0)*25600 + q] = o;
        m = b.x - s0; s0 = (m > 1.f) ? 1.f : 0.f; o.x = (unsigned char)(m > 1.f);
        m = b.y - s1; s1 = (m > 1.f) ? 1.f : 0.f; o.y = (unsigned char)(m > 1.f);
        m = b.z - s2; s2 = (m > 1.f) ? 1.f : 0.f; o.z = (unsigned char)(m > 1.f);
        m = b.w - s3; s3 = (m > 1.f) ? 1.f : 0.f; o.w = (unsigned char)(m > 1.f);
        out[(size_t)(t+1)*25600 + q] = o;
    }
}

// ---------------- k6: FC, 16 (t,b) pairs per block -------------------------
__global__ __launch_bounds__(320) void k_fc(const float* __restrict__ Wh2) {
    __shared__ unsigned char sS[16*1600];
    int tb0 = blockIdx.x * 16;
    int o = threadIdx.x >> 5, lane = threadIdx.x & 31;
    for (int i = threadIdx.x; i < 16*1600; i += 320)
        sS[i] = g_spkh1[(size_t)tb0*1600 + i];
    __syncthreads();
    const float* w = Wh2 + o*1600;
    #pragma unroll 1
    for (int p = 0; p < 16; p++) {
        const unsigned char* s = &sS[p*1600];
        float acc = 0.f;
        for (int f = lane; f < 1600; f += 32) acc += (float)s[f] * w[f];
        #pragma unroll
        for (int off = 16; off; off >>= 1) acc += __shfl_down_sync(0xffffffffu, acc, off);
        if (lane == 0) g_fc[(tb0 + p)*10 + o] = acc;
    }
}

// ---------------- k7: output LIF scan + write spikes and mem ---------------
__global__ void k_lif3(float* __restrict__ out) {
    int i = blockIdx.x * blockDim.x + threadIdx.x;
    if (i >= BATCH*10) return;
    float spk = 0.f;
    for (int t = 0; t < STEPS; t++) {
        float mem = g_fc[t*640 + i] - spk;
        spk = (mem > 1.0f) ? 1.0f : 0.0f;
        out[t*640 + i] = spk;                    // out_spikes [100,64,10]
        out[STEPS*640 + t*640 + i] = mem;        // memh2      [100,64,10]
    }
}

// ---------------- launcher -------------------------------------------------
extern "C" void kernel_launch(void* const* d_in, const int* in_sizes, int n_in,
                              void* d_out, int out_size) {
    const float* x   = (const float*)d_in[0];   // [64,3,32,32]
    const float* Win = (const float*)d_in[1];   // [32,3,5,5]
    const float* Wh1 = (const float*)d_in[2];   // [64,32,5,5]
    const float* Wh2 = (const float*)d_in[3];   // [10,1600]
    float* out = (float*)d_out;

    static int cfg_done = 0;
    if (!cfg_done) {   // executes eagerly (not a stream op); idempotent
        cudaFuncSetAttribute(k_conv2, cudaFuncAttributeMaxDynamicSharedMemorySize, C2_DYN);
        cfg_done = 1;
    }

    k_fold  <<<288, 256>>>(Win, Wh1);
    k_spikes<<<(NSPK + 255)/256, 256>>>(x);
    k_conv1 <<<TB, 112>>>();
    k_lif1  <<<N1/256, 256>>>();
    k_conv2 <<<256, 256, C2_DYN>>>();
    k_lif2  <<<N2/4/256, 256>>>();
    k_fc    <<<TB/16, 320>>>(Wh2);
    k_lif3  <<<3, 256>>>(out);
}

// round 5
// speedup vs baseline: 2.2842x; 2.2842x over previous
#include <cuda_runtime.h>
#include <cstdint>
#include <cstddef>

typedef unsigned long long ull;

// ---------------- problem constants ----------------
#define STEPS 100
#define BATCH 64
#define NSPK  (STEPS*BATCH*3*32*32)   // 19,660,800
#define XSZ   (BATCH*3*32*32)         // 196,608
#define N1    (BATCH*32*14*14)        // 401,408  (layer-1 neurons per step)
#define N2    (BATCH*64*5*5)          // 102,400  (layer-2 neurons per step)
#define TB    (STEPS*BATCH)           // 6400

// ---------------- scratch (device globals; no cudaMalloc allowed) ----------
__device__ __align__(16) unsigned char g_spk0[NSPK];          // poisson spikes [t][b][c][h][w]
__device__ __align__(16) float g_curin[(size_t)STEPS*N1];     // [t][b][sp196][oc32]
__device__ unsigned int  g_spk1[(size_t)STEPS*BATCH*196];     // [t][b*196+sp] -> 32-bit oc mask
__device__ __align__(16) float g_curh1[(size_t)STEPS*N2];     // [t][b][oc64*25+sp]
__device__ __align__(16) unsigned char g_spkh1[(size_t)STEPS*N2];
__device__ float         g_fc[STEPS*BATCH*10];
__device__ __align__(16) float g_Wp1[3*36*32];                // pooled conv1 W [c][uv6x6][oc32]
__device__ __align__(16) float g_Wp2[32*36*64];               // pooled conv2 W [c][uv6x6][oc64]

// ---------------- packed f32x2 helpers (bit-exact fp32 pairs) --------------
__device__ __forceinline__ void ffma2(ull& d, ull a, ull b) {
    asm("fma.rn.f32x2 %0, %1, %2, %0;" : "+l"(d) : "l"(a), "l"(b));
}
__device__ __forceinline__ void fadd2(ull& d, ull a) {
    asm("add.rn.f32x2 %0, %0, %1;" : "+l"(d) : "l"(a));
}
__device__ __forceinline__ ull pack_dup(float f) {
    ull p; asm("mov.b64 %0, {%1, %1};" : "=l"(p) : "f"(f)); return p;
}
__device__ __forceinline__ void unpack2(ull p, float& lo, float& hi) {
    asm("mov.b64 {%0, %1}, %2;" : "=f"(lo), "=f"(hi) : "l"(p));
}

// ---------------- threefry2x32 (JAX-exact, partitionable path) -------------
__device__ __forceinline__ uint2 threefry2x32(uint32_t k0, uint32_t k1,
                                              uint32_t x0, uint32_t x1) {
    uint32_t ks0 = k0, ks1 = k1, ks2 = k0 ^ k1 ^ 0x1BD11BDAu;
    x0 += ks0; x1 += ks1;
#define TFR(r) { x0 += x1; x1 = (x1 << (r)) | (x1 >> (32 - (r))); x1 ^= x0; }
    TFR(13) TFR(15) TFR(26) TFR(6)
    x0 += ks1; x1 += ks2 + 1u;
    TFR(17) TFR(29) TFR(16) TFR(24)
    x0 += ks2; x1 += ks0 + 2u;
    TFR(13) TFR(15) TFR(26) TFR(6)
    x0 += ks0; x1 += ks1 + 3u;
    TFR(17) TFR(29) TFR(16) TFR(24)
    x0 += ks1; x1 += ks2 + 4u;
    TFR(13) TFR(15) TFR(26) TFR(6)
    x0 += ks2; x1 += ks0 + 5u;
#undef TFR
    return make_uint2(x0, x1);
}

// ---------------- k0: fold avgpool(2x2,*0.25) into conv weights ------------
__global__ void k_fold(const float* __restrict__ Win, const float* __restrict__ Wh1) {
    int i = blockIdx.x * blockDim.x + threadIdx.x;
    if (i < 3*36*32) {
        int oc = i & 31; int r = i >> 5; int uv = r % 36; int c = r / 36;
        int u = uv / 6, v = uv % 6;
        float s = 0.f;
        #pragma unroll
        for (int dh = 0; dh < 2; dh++)
            #pragma unroll
            for (int dw = 0; dw < 2; dw++) {
                int kh = u - dh, kw = v - dw;
                if (kh >= 0 && kh < 5 && kw >= 0 && kw < 5)
                    s += Win[(oc*3 + c)*25 + kh*5 + kw];
            }
        g_Wp1[i] = 0.25f * s;
    }
    if (i < 32*36*64) {
        int oc = i & 63; int r = i >> 6; int uv = r % 36; int c = r / 36;
        int u = uv / 6, v = uv % 6;
        float s = 0.f;
        #pragma unroll
        for (int dh = 0; dh < 2; dh++)
            #pragma unroll
            for (int dw = 0; dw < 2; dw++) {
                int kh = u - dh, kw = v - dw;
                if (kh >= 0 && kh < 5 && kw >= 0 && kw < 5)
                    s += Wh1[(oc*32 + c)*25 + kh*5 + kw];
            }
        g_Wp2[i] = 0.25f * s;
    }
}

// ---------------- k1: poisson spikes, ILP-4 --------------------------------
__global__ void k_spikes(const float* __restrict__ x) {
    int q = blockIdx.x * 256 + threadIdx.x;      // quad index < NSPK/4
    int i0 = q << 2;
    const float4 xv = *(const float4*)&x[i0 % XSZ];   // XSZ % 4 == 0: no wrap
    uint2 r0 = threefry2x32(0u, 1u, 0u, (uint32_t)(i0 + 0));
    uint2 r1 = threefry2x32(0u, 1u, 0u, (uint32_t)(i0 + 1));
    uint2 r2 = threefry2x32(0u, 1u, 0u, (uint32_t)(i0 + 2));
    uint2 r3 = threefry2x32(0u, 1u, 0u, (uint32_t)(i0 + 3));
    uchar4 o;
    float u;
    u = __uint_as_float(((r0.x ^ r0.y) >> 9) | 0x3f800000u) - 1.0f; o.x = (u < xv.x * 2.0f);
    u = __uint_as_float(((r1.x ^ r1.y) >> 9) | 0x3f800000u) - 1.0f; o.y = (u < xv.y * 2.0f);
    u = __uint_as_float(((r2.x ^ r2.y) >> 9) | 0x3f800000u) - 1.0f; o.z = (u < xv.z * 2.0f);
    u = __uint_as_float(((r3.x ^ r3.y) >> 9) | 0x3f800000u) - 1.0f; o.w = (u < xv.w * 2.0f);
    ((uchar4*)g_spk0)[q] = o;
}

// ---------------- k2: conv1+pool, f32x2, 196 workers = (oc-half, sp-pair) --
__global__ __launch_bounds__(224) void k_conv1(void) {
    __shared__ float sIn[3*32*32];
    __shared__ __align__(16) float sW[3*36*32];
    int tb = blockIdx.x;
    int tid = threadIdx.x;
    const uchar4* inp = (const uchar4*)(g_spk0 + (size_t)tb * 3072);
    for (int i = tid; i < 768; i += 224) {
        uchar4 b4 = inp[i];
        float4 f4 = make_float4((float)b4.x, (float)b4.y, (float)b4.z, (float)b4.w);
        *(float4*)&sIn[i*4] = f4;
    }
    for (int i = tid; i < 3456; i += 224) sW[i] = g_Wp1[i];
    __syncthreads();
    if (tid >= 196) return;

    int oh  = tid / 98;               // oc half: oc = oh*16 .. +15
    int spi = tid - oh*98;            // sp pair: sp0 = 2*spi, sp1 = 2*spi+1
    int sp0 = 2*spi;
    int ph = sp0 / 14, pw = sp0 % 14;
    int ia = ph*64 + pw*2;            // (2ph)*32 + 2pw ; sp1 input base = ia+2
    ull accA[8], accB[8];
    #pragma unroll
    for (int j = 0; j < 8; j++) { accA[j] = 0ull; accB[j] = 0ull; }

    #pragma unroll 1
    for (int c = 0; c < 3; c++) {
        const float* sIc = &sIn[c*1024 + ia];
        const float* wc  = &sW[c*1152 + oh*16];
        #pragma unroll 1
        for (int u = 0; u < 6; u++) {
            #pragma unroll
            for (int v = 0; v < 6; v++) {
                ull sa = pack_dup(sIc[u*32 + v]);
                ull sb = pack_dup(sIc[u*32 + v + 2]);
                const ull* w = (const ull*)&wc[(u*6 + v)*32];
                #pragma unroll
                for (int j = 0; j < 8; j++) {
                    ull wj = w[j];
                    ffma2(accA[j], wj, sa);
                    ffma2(accB[j], wj, sb);
                }
            }
        }
    }
    ull* oA = (ull*)&g_curin[(size_t)tb*6272 + sp0*32 + oh*16];
    ull* oB = (ull*)&g_curin[(size_t)tb*6272 + (sp0+1)*32 + oh*16];
    #pragma unroll
    for (int j = 0; j < 8; j++) { oA[j] = accA[j]; oB[j] = accB[j]; }
}

// ---------------- k3: LIF scan layer 1 -> ballot bitmasks ------------------
__global__ void k_lif1(void) {
    int n = blockIdx.x*256 + threadIdx.x;       // < 401408 ; n = (b*196+sp)*32+oc
    int lane = threadIdx.x & 31;
    int bs = n >> 5;                            // b*196 + sp
    const float* cur = g_curin + n;
    unsigned* out = g_spk1 + bs;
    float spk = 0.f;
    #pragma unroll 1
    for (int t = 0; t < STEPS; t += 4) {
        float c0 = cur[(size_t)(t+0)*N1];
        float c1 = cur[(size_t)(t+1)*N1];
        float c2 = cur[(size_t)(t+2)*N1];
        float c3 = cur[(size_t)(t+3)*N1];
        float mem; unsigned m0, m1, m2, m3;
        mem = c0 - spk; spk = (mem > 1.f) ? 1.f : 0.f; m0 = __ballot_sync(0xffffffffu, mem > 1.f);
        mem = c1 - spk; spk = (mem > 1.f) ? 1.f : 0.f; m1 = __ballot_sync(0xffffffffu, mem > 1.f);
        mem = c2 - spk; spk = (mem > 1.f) ? 1.f : 0.f; m2 = __ballot_sync(0xffffffffu, mem > 1.f);
        mem = c3 - spk; spk = (mem > 1.f) ? 1.f : 0.f; m3 = __ballot_sync(0xffffffffu, mem > 1.f);
        if (lane == 0) {
            out[(size_t)(t+0)*12544] = m0;
            out[(size_t)(t+1)*12544] = m1;
            out[(size_t)(t+2)*12544] = m2;
            out[(size_t)(t+3)*12544] = m3;
        }
    }
}

// ---------------- k4: conv2+pool, mask-windowed sparse, t-group of 4 -------
// block = (t-group, b): stage per-channel 64-oc weights once per 4 timesteps
__global__ __launch_bounds__(256) void k_conv2(void) {
    __shared__ __align__(16) float sW[36*64];   // per-channel weights
    __shared__ unsigned sMask4[4*196];          // oc-masks for 4 t
    __shared__ unsigned sRow[4][32*14];         // per-t per-channel row masks

    int tid = threadIdx.x;
    int b   = blockIdx.x & 63;
    int tg  = blockIdx.x >> 6;                  // 0..24
    int t0  = tg * 4;

    for (int i = tid; i < 4*196; i += 256) {
        int tt = i / 196, sp = i - tt*196;
        sMask4[i] = g_spk1[(size_t)(t0 + tt)*12544 + b*196 + sp];
    }
    __syncthreads();
    if (tid < 224) {                            // transpose to row bitmasks
        int c = tid & 31; int rp = tid >> 5;    // rp 0..6
        #pragma unroll
        for (int tt = 0; tt < 4; tt++) {
            const unsigned* mk = &sMask4[tt*196];
            #pragma unroll
            for (int rr = 0; rr < 2; rr++) {
                int ih = rp*2 + rr;
                unsigned m = 0;
                #pragma unroll
                for (int iw = 0; iw < 14; iw++)
                    m |= ((mk[ih*14 + iw] >> c) & 1u) << iw;
                sRow[tt][c*14 + ih] = m;
            }
        }
    }

    int active = (tid < 200);
    int sp = tid >> 3, og = tid & 7;            // sp 0..24, oc octet og*8..+7
    int ph = sp / 5, pw = sp % 5;
    int shift = 2*pw;
    ull acc[4][4];
    #pragma unroll
    for (int tt = 0; tt < 4; tt++)
        #pragma unroll
        for (int j = 0; j < 4; j++) acc[tt][j] = 0ull;

    #pragma unroll 1
    for (int c = 0; c < 32; c++) {
        __syncthreads();                        // prev gather done (and transpose, 1st iter)
        for (int i = tid; i < 576; i += 256)
            *(float4*)&sW[i*4] = *(const float4*)&g_Wp2[c*2304 + i*4];
        __syncthreads();
        if (active) {
            #pragma unroll
            for (int tt = 0; tt < 4; tt++) {
                const unsigned* rc = &sRow[tt][c*14 + 2*ph];
                #pragma unroll
                for (int u = 0; u < 6; u++) {
                    unsigned bits = (rc[u] >> shift) & 63u;
                    while (bits) {
                        int v = __ffs(bits) - 1; bits &= bits - 1;
                        const ull* w = (const ull*)&sW[(u*6 + v)*64 + og*8];
                        fadd2(acc[tt][0], w[0]); fadd2(acc[tt][1], w[1]);
                        fadd2(acc[tt][2], w[2]); fadd2(acc[tt][3], w[3]);
                    }
                }
            }
        }
    }

    if (active) {
        #pragma unroll
        for (int tt = 0; tt < 4; tt++) {
            size_t ob = (size_t)((t0 + tt)*64 + b)*1600 + (size_t)(og*8)*25 + sp;
            float f[8];
            unpack2(acc[tt][0], f[0], f[1]); unpack2(acc[tt][1], f[2], f[3]);
            unpack2(acc[tt][2], f[4], f[5]); unpack2(acc[tt][3], f[6], f[7]);
            #pragma unroll
            for (int j = 0; j < 8; j++) g_curh1[ob + j*25] = f[j];
        }
    }
}

// ---------------- k5: LIF scan layer 2 (float4, unroll2) -------------------
__global__ void k_lif2(void) {
    int q = blockIdx.x*256 + threadIdx.x;       // < 25600 float4-neurons
    const float4* cur = (const float4*)g_curh1;
    uchar4* out = (uchar4*)g_spkh1;
    float s0 = 0.f, s1 = 0.f, s2 = 0.f, s3 = 0.f;
    #pragma unroll 1
    for (int t = 0; t < STEPS; t += 2) {
        float4 a = cur[(size_t)(t+0)*25600 + q];
        float4 b = cur[(size_t)(t+1)*25600 + q];
        float m; uchar4 o;
        m = a.x - s0; s0 = (m > 1.f) ? 1.f : 0.f; o.x = (unsigned char)(m > 1.f);
        m = a.y - s1; s1 = (m > 1.f) ? 1.f : 0.f; o.y = (unsigned char)(m > 1.f);
        m = a.z - s2; s2 = (m > 1.f) ? 1.f : 0.f; o.z = (unsigned char)(m > 1.f);
        m = a.w - s3; s3 = (m > 1.f) ? 1.f : 0.f; o.w = (unsigned char)(m > 1.f);
        out[(size_t)(t+0)*25600 + q] = o;
        m = b.x - s0; s0 = (m > 1.f) ? 1.f : 0.f; o.x = (unsigned char)(m > 1.f);
        m = b.y - s1; s1 = (m > 1.f) ? 1.f : 0.f; o.y = (unsigned char)(m > 1.f);
        m = b.z - s2; s2 = (m > 1.f) ? 1.f : 0.f; o.z = (unsigned char)(m > 1.f);
        m = b.w - s3; s3 = (m > 1.f) ? 1.f : 0.f; o.w = (unsigned char)(m > 1.f);
        out[(size_t)(t+1)*25600 + q] = o;
    }
}

// ---------------- k6: FC, 16 (t,b) pairs per block -------------------------
__global__ __launch_bounds__(320) void k_fc(const float* __restrict__ Wh2) {
    __shared__ unsigned char sS[16*1600];
    int tb0 = blockIdx.x * 16;
    int o = threadIdx.x >> 5, lane = threadIdx.x & 31;
    for (int i = threadIdx.x; i < 16*1600/16; i += 320)
        *(uint4*)&sS[i*16] = *(const uint4*)&g_spkh1[(size_t)tb0*1600 + i*16];
    __syncthreads();
    const float* w = Wh2 + o*1600;
    #pragma unroll 1
    for (int p = 0; p < 16; p++) {
        const unsigned char* s = &sS[p*1600];
        float acc = 0.f;
        for (int f = lane; f < 1600; f += 32) acc += (float)s[f] * w[f];
        #pragma unroll
        for (int off = 16; off; off >>= 1) acc += __shfl_down_sync(0xffffffffu, acc, off);
        if (lane == 0) g_fc[(tb0 + p)*10 + o] = acc;
    }
}

// ---------------- k7: output LIF scan + write spikes and mem ---------------
__global__ void k_lif3(float* __restrict__ out) {
    int i = blockIdx.x * blockDim.x + threadIdx.x;
    if (i >= BATCH*10) return;
    float spk = 0.f;
    for (int t = 0; t < STEPS; t++) {
        float mem = g_fc[t*640 + i] - spk;
        spk = (mem > 1.0f) ? 1.0f : 0.0f;
        out[t*640 + i] = spk;                    // out_spikes [100,64,10]
        out[STEPS*640 + t*640 + i] = mem;        // memh2      [100,64,10]
    }
}

// ---------------- launcher -------------------------------------------------
extern "C" void kernel_launch(void* const* d_in, const int* in_sizes, int n_in,
                              void* d_out, int out_size) {
    const float* x   = (const float*)d_in[0];   // [64,3,32,32]
    const float* Win = (const float*)d_in[1];   // [32,3,5,5]
    const float* Wh1 = (const float*)d_in[2];   // [64,32,5,5]
    const float* Wh2 = (const float*)d_in[3];   // [10,1600]
    float* out = (float*)d_out;

    k_fold  <<<288, 256>>>(Win, Wh1);
    k_spikes<<<NSPK/4/256, 256>>>(x);
    k_conv1 <<<TB, 224>>>();
    k_lif1  <<<N1/256, 256>>>();
    k_conv2 <<<1600, 256>>>();
    k_lif2  <<<N2/4/256, 256>>>();
    k_fc    <<<TB/16, 320>>>(Wh2);
    k_lif3  <<<3, 256>>>(out);
}